// round 17
// baseline (speedup 1.0000x reference)
#include <cuda_runtime.h>
#include <cuda_fp16.h>
#include <cstdint>
#include <math.h>

// DecoderLayer fwd: B=4, L=1024, D=1024, H=16, dh=64, Dff=4096, fp32 I/O.
// R15: operands pre-converted to fp16 ONCE (X, weights via tiny cvt kernels;
//      Hb written fp16 by FFN1 epilogue; X1h by LN1). GEMMs stage fp16 tiles
//      (80B-padded rows -> conflict-free LDS, no swizzle, no in-loop cvt).
//      Attention = R12 (tf32 QK, cp.async dbuf). LN writes optional fp16 copy.

#define BB  4
#define LL  1024
#define DD  1024
#define HH  16
#define DH  64
#define DFF 4096
#define MM  (BB*LL)   // 4096

// Scratch (allocation-free: __device__ globals)
__device__ float  g_Q[MM*DD];
__device__ float  g_K[MM*DD];
__device__ float  g_V[MM*DD];
__device__ float  g_ctx[MM*DD];
__device__ float  g_X1[MM*DD];
__device__ float  g_Y[MM*DD];
__device__ float  g_Y2[MM*DD];
__device__ __half g_Xh[MM*DD];
__device__ __half g_X1h[MM*DD];
__device__ __half g_Hbh[(size_t)MM*DFF];
__device__ __half g_wqh[DD*DD];
__device__ __half g_wkh[DD*DD];
__device__ __half g_wvh[DD*DD];
__device__ __half g_w1h[(size_t)DFF*DD];
__device__ __half g_w2h[(size_t)DD*DFF];

static __device__ __forceinline__ float selu_f(float x) {
    const float scale = 1.0507009873554804934193349852946f;
    const float alpha = 1.6732632423543772848170429916717f;
    return x > 0.f ? scale * x : scale * alpha * (__expf(x) - 1.f);
}

static __device__ __forceinline__ uint32_t smem_u32(const void* p) {
    uint32_t a;
    asm("{ .reg .u64 t; cvta.to.shared.u64 t, %1; cvt.u32.u64 %0, t; }"
        : "=r"(a) : "l"(p));
    return a;
}

#define CP16(dst, src) \
    asm volatile("cp.async.cg.shared.global [%0], [%1], 16;" \
                 :: "r"((uint32_t)(dst)), "l"(src) : "memory")
#define CP_COMMIT() asm volatile("cp.async.commit_group;" ::: "memory")
#define CP_WAIT(n)  asm volatile("cp.async.wait_group %0;" :: "n"(n) : "memory")

static __device__ __forceinline__ void mma_tf32(float* c, const uint32_t* a,
                                                const uint32_t* b) {
    asm volatile(
        "mma.sync.aligned.m16n8k8.row.col.f32.tf32.tf32.f32 "
        "{%0,%1,%2,%3}, {%4,%5,%6,%7}, {%8,%9}, {%0,%1,%2,%3};"
        : "+f"(c[0]), "+f"(c[1]), "+f"(c[2]), "+f"(c[3])
        : "r"(a[0]), "r"(a[1]), "r"(a[2]), "r"(a[3]), "r"(b[0]), "r"(b[1]));
}

static __device__ __forceinline__ void mma_f16(float* c, const uint32_t* a,
                                               const uint32_t* b) {
    asm volatile(
        "mma.sync.aligned.m16n8k16.row.col.f32.f16.f16.f32 "
        "{%0,%1,%2,%3}, {%4,%5,%6,%7}, {%8,%9}, {%0,%1,%2,%3};"
        : "+f"(c[0]), "+f"(c[1]), "+f"(c[2]), "+f"(c[3])
        : "r"(a[0]), "r"(a[1]), "r"(a[2]), "r"(a[3]), "r"(b[0]), "r"(b[1]));
}

static __device__ __forceinline__ float tf32r(float x) {
    uint32_t u;
    asm("cvt.rna.tf32.f32 %0, %1;" : "=r"(u) : "f"(x));
    return __uint_as_float(u);
}

// ---------------------------------------------------------------------------
// fp32 -> fp16 conversion (grid-stride-free: exact sizing). 4 elems/thread.
// ---------------------------------------------------------------------------
__global__ __launch_bounds__(256)
void cvt_f32_f16(const float* __restrict__ src, __half* __restrict__ dst,
                 int n)
{
    const int i = (blockIdx.x * 256 + threadIdx.x) * 4;
    if (i < n) {
        float4 v = *(const float4*)&src[i];
        __half2* d = (__half2*)&dst[i];
        d[0] = __floats2half2_rn(v.x, v.y);
        d[1] = __floats2half2_rn(v.z, v.w);
    }
}

// ---------------------------------------------------------------------------
// fp16 mma.sync GEMM: C[M,N] = A[M,K] @ B[N,K]^T  (both fp16, K-major)
// CTA 128x128, BK=32, 128 threads = 4 warps (2Mx2N), warp tile 64x64.
// Tiles: 128 rows x 32 fp16 (64B data) padded to 80B/row -> LDS addr
// 20*row + w mod 32 is conflict-free across g=0..7 with NO swizzle.
// 3-stage cp.async. 1 fp16 MMA per (mt,nt) per K=16 step; no in-loop cvt.
// MODE 1: Ch = fp16(selu(acc+bias))
// MODE 3: QKV — blockIdx.z selects (B0,C0)/(B1,C1)/(B2,C2), fp32 store.
// MODE 4: split-K(2) — blockIdx.z selects k-half and C0/C1, fp32 store.
// ---------------------------------------------------------------------------
#define HROW     20                   // 32-bit words per padded row (80B)
#define HTILE_B  (128 * 80)           // 10240 B per tile
#define HBUF     (2 * HTILE_B)        // A + B per stage
#define HSTAGE   3
#define GEMMH_SMEM (HSTAGE * HBUF)    // 61440

template<int MODE>
__global__ __launch_bounds__(128, 2)
void gemm_h(const __half* __restrict__ A,
            const __half* __restrict__ B0, const __half* __restrict__ B1,
            const __half* __restrict__ B2,
            float* __restrict__ C0, float* __restrict__ C1,
            float* __restrict__ C2, __half* __restrict__ Ch,
            const float* __restrict__ bias,
            int M, int N, int K)
{
    extern __shared__ char smem[];
    const uint32_t sb = smem_u32(smem);
    const int tid  = threadIdx.x;
    const int wid  = tid >> 5;
    const int lane = tid & 31;
    const int g    = lane >> 2;
    const int tg   = lane & 3;
    const int wm   = wid & 1;
    const int wn   = wid >> 1;
    const int m0   = blockIdx.y * 128;
    const int n0   = blockIdx.x * 128;

    const __half* Bw = B0;
    float*        C  = C0;
    if (MODE == 3) {
        if (blockIdx.z == 1)      { Bw = B1; C = C1; }
        else if (blockIdx.z == 2) { Bw = B2; C = C2; }
    }
    int keff = K, koff = 0;
    if (MODE == 4) {
        keff = K >> 1;
        koff = blockIdx.z * keff;
        if (blockIdx.z == 1) C = C1;
    }

    auto stage = [&](int s, int k0) {
        const uint32_t ab = sb + s * HBUF;
#pragma unroll
        for (int t = 0; t < 4; t++) {
            int idx = tid + t * 128;            // 0..511
            int row = idx >> 2;                 // 0..127
            int c   = idx & 3;                  // 16B chunk (8 fp16)
            CP16(ab + row * 80 + c * 16,
                 A  + (size_t)(m0 + row) * K + koff + k0 + c * 8);
            CP16(ab + HTILE_B + row * 80 + c * 16,
                 Bw + (size_t)(n0 + row) * K + koff + k0 + c * 8);
        }
        CP_COMMIT();
    };

    const int rowA = wm * 64 + g;
    const int colB = wn * 64 + g;

    float acc[4][8][4];
#pragma unroll
    for (int mt = 0; mt < 4; mt++)
#pragma unroll
        for (int nt = 0; nt < 8; nt++)
#pragma unroll
            for (int r = 0; r < 4; r++) acc[mt][nt][r] = 0.f;

    const int nch = keff / 32;
    stage(0, 0);
    if (nch > 1) stage(1, 32);

    for (int i = 0; i < nch; i++) {
        const int buf = i % HSTAGE;
        if (i + 1 < nch) { CP_WAIT(1); } else { CP_WAIT(0); }
        __syncthreads();
        if (i + 2 < nch) stage((i + 2) % HSTAGE, (i + 2) * 32);

        const uint32_t* As = (const uint32_t*)(smem + buf * HBUF);
        const uint32_t* Bs = (const uint32_t*)(smem + buf * HBUF + HTILE_B);

#pragma unroll
        for (int s = 0; s < 2; s++) {           // K=16 steps
            const int w0 = 8 * s + tg;
            const int w1 = 8 * s + 4 + tg;
            uint32_t a[4][4];
#pragma unroll
            for (int mt = 0; mt < 4; mt++) {
                const int r0 = (rowA + mt * 16) * HROW;
                const int r8 = r0 + 8 * HROW;
                a[mt][0] = As[r0 + w0];
                a[mt][1] = As[r8 + w0];
                a[mt][2] = As[r0 + w1];
                a[mt][3] = As[r8 + w1];
            }
            uint32_t b[8][2];
#pragma unroll
            for (int nt = 0; nt < 8; nt++) {
                const int rr = (colB + nt * 8) * HROW;
                b[nt][0] = Bs[rr + w0];
                b[nt][1] = Bs[rr + w1];
            }
#pragma unroll
            for (int mt = 0; mt < 4; mt++)
#pragma unroll
                for (int nt = 0; nt < 8; nt++)
                    mma_f16(acc[mt][nt], a[mt], b[nt]);
        }
    }

#pragma unroll
    for (int mt = 0; mt < 4; mt++) {
        const int r0 = m0 + wm * 64 + mt * 16 + g;
#pragma unroll
        for (int nt = 0; nt < 8; nt++) {
            const int col = n0 + wn * 64 + nt * 8 + tg * 2;
            float v0 = acc[mt][nt][0], v1 = acc[mt][nt][1];
            float v2 = acc[mt][nt][2], v3 = acc[mt][nt][3];
            if (MODE == 1) {
                v0 = selu_f(v0 + bias[col]);     v1 = selu_f(v1 + bias[col + 1]);
                v2 = selu_f(v2 + bias[col]);     v3 = selu_f(v3 + bias[col + 1]);
                *(__half2*)&Ch[(size_t)r0 * N + col] = __floats2half2_rn(v0, v1);
                *(__half2*)&Ch[(size_t)(r0 + 8) * N + col] = __floats2half2_rn(v2, v3);
            } else {
                *(float2*)&C[(size_t)r0 * N + col]       = make_float2(v0, v1);
                *(float2*)&C[(size_t)(r0 + 8) * N + col] = make_float2(v2, v3);
            }
        }
    }
}

// ---------------------------------------------------------------------------
// Tensor-core flash attention (R12, unchanged). grid=(16, B*H), block=128.
// ---------------------------------------------------------------------------
#define SQK 68
#define SV  72
#define STG_F (64*SQK + 64*SV)                   // floats per K/V stage
#define ATT_SMEM ((64*SQK + 2*STG_F) * 4)        // 91136 B

__global__ __launch_bounds__(128)
void attn_tc(const float* __restrict__ Q, const float* __restrict__ K,
             const float* __restrict__ V, float* __restrict__ O)
{
    extern __shared__ float sm[];
    float* Qh = sm;
    float* St = Qh + 64*SQK;          // stage s: Kr=St+s*STG_F, Vs=Kr+64*SQK

    const int qb = (int)gridDim.x - 1 - (int)blockIdx.x;  // heavy blocks first
    const int q0 = qb * 64;
    const int bh = blockIdx.y;
    const int b  = bh >> 4;
    const int h  = bh & 15;
    const size_t base = (size_t)b * LL * DD + (size_t)h * DH;

    const int tid  = threadIdx.x;
    const int lane = tid & 31;
    const int g    = lane >> 2;
    const int tg   = lane & 3;
    const int qw   = (tid >> 5) * 16;

    const uint32_t stb = smem_u32(St);

    auto prefetch = [&](int s, int k0) {
        const uint32_t kb = stb + (uint32_t)(s * STG_F) * 4u;
        const uint32_t vb = kb + 64u * SQK * 4u;
#pragma unroll
        for (int i = 0; i < 8; i++) {
            int idx = tid + i * 128;
            int r = idx >> 4, c4 = (idx & 15) * 4;
            CP16(kb + (uint32_t)(r * SQK + c4) * 4u,
                 K + base + (size_t)(k0 + r) * DD + c4);
            CP16(vb + (uint32_t)(r * SV + c4) * 4u,
                 V + base + (size_t)(k0 + r) * DD + c4);
        }
        CP_COMMIT();
    };

    prefetch(0, 0);

#pragma unroll
    for (int i = 0; i < 8; i++) {
        int idx = tid + i * 128;
        int r = idx >> 4, c4 = (idx & 15) * 4;
        float4 v = *(const float4*)&Q[base + (size_t)(q0 + r) * DD + c4];
        float4 hi;
        hi.x = tf32r(v.x * 0.125f);
        hi.y = tf32r(v.y * 0.125f);
        hi.z = tf32r(v.z * 0.125f);
        hi.w = tf32r(v.w * 0.125f);
        *(float4*)&Qh[r * SQK + c4] = hi;
    }

    float m0r = -1e30f, m1r = -1e30f, l0r = 0.f, l1r = 0.f;
    float oacc[8][4];
#pragma unroll
    for (int nb = 0; nb < 8; nb++)
#pragma unroll
        for (int r = 0; r < 4; r++) oacc[nb][r] = 0.f;

    const int ntile = qb + 1;
    for (int kt = 0; kt < ntile; kt++) {
        const int k0 = kt * 64;
        if (kt + 1 < ntile) {
            prefetch((kt + 1) & 1, (kt + 1) * 64);
            CP_WAIT(1);
        } else {
            CP_WAIT(0);
        }
        __syncthreads();

        const float* Kr = St + (kt & 1) * STG_F;
        const float* Vs = Kr + 64 * SQK;

        float sacc[8][4];
#pragma unroll
        for (int nb = 0; nb < 8; nb++)
#pragma unroll
            for (int r = 0; r < 4; r++) sacc[nb][r] = 0.f;

#pragma unroll
        for (int ks = 0; ks < 8; ks++) {
            const int d0 = ks * 8 + tg;
            uint32_t ah[4];
            ah[0] = __float_as_uint(Qh[(qw + g    ) * SQK + d0    ]);
            ah[1] = __float_as_uint(Qh[(qw + g + 8) * SQK + d0    ]);
            ah[2] = __float_as_uint(Qh[(qw + g    ) * SQK + d0 + 4]);
            ah[3] = __float_as_uint(Qh[(qw + g + 8) * SQK + d0 + 4]);
#pragma unroll
            for (int nb = 0; nb < 8; nb++) {
                uint32_t bh2[2];
                bh2[0] = __float_as_uint(tf32r(Kr[(nb * 8 + g) * SQK + d0    ]));
                bh2[1] = __float_as_uint(tf32r(Kr[(nb * 8 + g) * SQK + d0 + 4]));
                mma_tf32(sacc[nb], ah, bh2);
            }
        }

        if (k0 == q0) {
#pragma unroll
            for (int nb = 0; nb < 8; nb++) {
                const int col = nb * 8 + 2 * tg;
                const int r0 = qw + g, r1 = r0 + 8;
                if (col     > r0) sacc[nb][0] = -1e30f;
                if (col + 1 > r0) sacc[nb][1] = -1e30f;
                if (col     > r1) sacc[nb][2] = -1e30f;
                if (col + 1 > r1) sacc[nb][3] = -1e30f;
            }
        }

        float mx0 = -1e30f, mx1 = -1e30f;
#pragma unroll
        for (int nb = 0; nb < 8; nb++) {
            mx0 = fmaxf(mx0, fmaxf(sacc[nb][0], sacc[nb][1]));
            mx1 = fmaxf(mx1, fmaxf(sacc[nb][2], sacc[nb][3]));
        }
        mx0 = fmaxf(mx0, __shfl_xor_sync(0xffffffffu, mx0, 1));
        mx0 = fmaxf(mx0, __shfl_xor_sync(0xffffffffu, mx0, 2));
        mx1 = fmaxf(mx1, __shfl_xor_sync(0xffffffffu, mx1, 1));
        mx1 = fmaxf(mx1, __shfl_xor_sync(0xffffffffu, mx1, 2));

        const float nm0 = fmaxf(m0r, mx0), nm1 = fmaxf(m1r, mx1);
        const float al0 = __expf(m0r - nm0), al1 = __expf(m1r - nm1);
        float rs0 = 0.f, rs1 = 0.f;
#pragma unroll
        for (int nb = 0; nb < 8; nb++) {
            sacc[nb][0] = __expf(sacc[nb][0] - nm0);
            sacc[nb][1] = __expf(sacc[nb][1] - nm0);
            sacc[nb][2] = __expf(sacc[nb][2] - nm1);
            sacc[nb][3] = __expf(sacc[nb][3] - nm1);
            rs0 += sacc[nb][0] + sacc[nb][1];
            rs1 += sacc[nb][2] + sacc[nb][3];
        }
        rs0 += __shfl_xor_sync(0xffffffffu, rs0, 1);
        rs0 += __shfl_xor_sync(0xffffffffu, rs0, 2);
        rs1 += __shfl_xor_sync(0xffffffffu, rs1, 1);
        rs1 += __shfl_xor_sync(0xffffffffu, rs1, 2);
        l0r = l0r * al0 + rs0;
        l1r = l1r * al1 + rs1;
        m0r = nm0; m1r = nm1;
#pragma unroll
        for (int nb = 0; nb < 8; nb++) {
            oacc[nb][0] *= al0; oacc[nb][1] *= al0;
            oacc[nb][2] *= al1; oacc[nb][3] *= al1;
        }

#pragma unroll
        for (int ks2 = 0; ks2 < 8; ks2++) {
            const int sA = (lane & 28) | (tg >> 1);
            const int sB = sA + 2;
            const float q0v = __shfl_sync(0xffffffffu, sacc[ks2][0], sA);
            const float q1v = __shfl_sync(0xffffffffu, sacc[ks2][1], sA);
            const float q2v = __shfl_sync(0xffffffffu, sacc[ks2][2], sA);
            const float q3v = __shfl_sync(0xffffffffu, sacc[ks2][3], sA);
            const float r0v = __shfl_sync(0xffffffffu, sacc[ks2][0], sB);
            const float r1v = __shfl_sync(0xffffffffu, sacc[ks2][1], sB);
            const float r2v = __shfl_sync(0xffffffffu, sacc[ks2][2], sB);
            const float r3v = __shfl_sync(0xffffffffu, sacc[ks2][3], sB);
            const bool oddc = (tg & 1);
            uint32_t aP[4];
            aP[0] = __float_as_uint(oddc ? q1v : q0v);
            aP[1] = __float_as_uint(oddc ? q3v : q2v);
            aP[2] = __float_as_uint(oddc ? r1v : r0v);
            aP[3] = __float_as_uint(oddc ? r3v : r2v);
#pragma unroll
            for (int nb2 = 0; nb2 < 8; nb2++) {
                uint32_t bV[2];
                bV[0] = __float_as_uint(Vs[(ks2 * 8 + tg    ) * SV + nb2 * 8 + g]);
                bV[1] = __float_as_uint(Vs[(ks2 * 8 + tg + 4) * SV + nb2 * 8 + g]);
                mma_tf32(oacc[nb2], aP, bV);
            }
        }
        __syncthreads();
    }

    const float inv0 = 1.f / l0r, inv1 = 1.f / l1r;
    const int r0 = q0 + qw + g, r1 = r0 + 8;
#pragma unroll
    for (int nb = 0; nb < 8; nb++) {
        const int c = nb * 8 + tg * 2;
        *(float2*)&O[base + (size_t)r0 * DD + c] =
            make_float2(oacc[nb][0] * inv0, oacc[nb][1] * inv0);
        *(float2*)&O[base + (size_t)r1 * DD + c] =
            make_float2(oacc[nb][2] * inv1, oacc[nb][3] * inv1);
    }
}

// ---------------------------------------------------------------------------
// LayerNorm over last dim (1024). Input = x [+ add] [+ add2] [+ brow[col]].
// Optional fp16 copy of the output (out16 != nullptr).
// ---------------------------------------------------------------------------
__global__ __launch_bounds__(256)
void ln_kernel(const float* __restrict__ x, const float* __restrict__ add,
               const float* __restrict__ add2, const float* __restrict__ brow,
               const float* __restrict__ g, const float* __restrict__ bta,
               float* __restrict__ out, __half* __restrict__ out16)
{
    const int row = blockIdx.x;
    const int tid = threadIdx.x;
    const size_t off = (size_t)row * DD + tid * 4;

    float4 v = *(const float4*)&x[off];
    if (add != nullptr) {
        float4 a = *(const float4*)&add[off];
        v.x += a.x; v.y += a.y; v.z += a.z; v.w += a.w;
    }
    if (add2 != nullptr) {
        float4 a = *(const float4*)&add2[off];
        v.x += a.x; v.y += a.y; v.z += a.z; v.w += a.w;
    }
    if (brow != nullptr) {
        float4 a = *(const float4*)&brow[tid * 4];
        v.x += a.x; v.y += a.y; v.z += a.z; v.w += a.w;
    }
    float s1 = v.x + v.y + v.z + v.w;
    float s2 = v.x*v.x + v.y*v.y + v.z*v.z + v.w*v.w;
#pragma unroll
    for (int o2 = 16; o2; o2 >>= 1) {
        s1 += __shfl_xor_sync(0xffffffffu, s1, o2);
        s2 += __shfl_xor_sync(0xffffffffu, s2, o2);
    }
    __shared__ float r1[8], r2[8], mb[2];
    const int lane = tid & 31, wd = tid >> 5;
    if (lane == 0) { r1[wd] = s1; r2[wd] = s2; }
    __syncthreads();
    if (tid == 0) {
        float a = 0.f, c = 0.f;
#pragma unroll
        for (int w = 0; w < 8; w++) { a += r1[w]; c += r2[w]; }
        const float mean = a * (1.f / DD);
        const float var  = c * (1.f / DD) - mean * mean;
        mb[0] = mean;
        mb[1] = rsqrtf(var + 1e-5f);
    }
    __syncthreads();
    const float mean = mb[0], rstd = mb[1];

    float4 gg = *(const float4*)&g[tid * 4];
    float4 bb = *(const float4*)&bta[tid * 4];
    float4 r;
    r.x = (v.x - mean) * rstd * gg.x + bb.x;
    r.y = (v.y - mean) * rstd * gg.y + bb.y;
    r.z = (v.z - mean) * rstd * gg.z + bb.z;
    r.w = (v.w - mean) * rstd * gg.w + bb.w;
    *(float4*)&out[off] = r;
    if (out16 != nullptr) {
        __half2* d = (__half2*)&out16[off];
        d[0] = __floats2half2_rn(r.x, r.y);
        d[1] = __floats2half2_rn(r.z, r.w);
    }
}

// ---------------------------------------------------------------------------
extern "C" void kernel_launch(void* const* d_in, const int* in_sizes, int n_in,
                              void* d_out, int out_size)
{
    const float* X     = (const float*)d_in[0];
    const float* wq    = (const float*)d_in[1];
    const float* wk    = (const float*)d_in[2];
    const float* wv    = (const float*)d_in[3];
    const float* ln1_g = (const float*)d_in[4];
    const float* ln1_b = (const float*)d_in[5];
    const float* w1    = (const float*)d_in[6];
    const float* b1    = (const float*)d_in[7];
    const float* w2    = (const float*)d_in[8];
    const float* b2    = (const float*)d_in[9];
    const float* ln2_g = (const float*)d_in[10];
    const float* ln2_b = (const float*)d_in[11];
    float* out = (float*)d_out;

    float *pQ, *pK, *pV, *pCtx, *pX1, *pY, *pY2;
    __half *pXh, *pX1h, *pHbh, *pWqh, *pWkh, *pWvh, *pW1h, *pW2h;
    cudaGetSymbolAddress((void**)&pQ,   g_Q);
    cudaGetSymbolAddress((void**)&pK,   g_K);
    cudaGetSymbolAddress((void**)&pV,   g_V);
    cudaGetSymbolAddress((void**)&pCtx, g_ctx);
    cudaGetSymbolAddress((void**)&pX1,  g_X1);
    cudaGetSymbolAddress((void**)&pY,   g_Y);
    cudaGetSymbolAddress((void**)&pY2,  g_Y2);
    cudaGetSymbolAddress((void**)&pXh,  g_Xh);
    cudaGetSymbolAddress((void**)&pX1h, g_X1h);
    cudaGetSymbolAddress((void**)&pHbh, g_Hbh);
    cudaGetSymbolAddress((void**)&pWqh, g_wqh);
    cudaGetSymbolAddress((void**)&pWkh, g_wkh);
    cudaGetSymbolAddress((void**)&pWvh, g_wvh);
    cudaGetSymbolAddress((void**)&pW1h, g_w1h);
    cudaGetSymbolAddress((void**)&pW2h, g_w2h);

    cudaFuncSetAttribute(gemm_h<1>, cudaFuncAttributeMaxDynamicSharedMemorySize, GEMMH_SMEM);
    cudaFuncSetAttribute(gemm_h<3>, cudaFuncAttributeMaxDynamicSharedMemorySize, GEMMH_SMEM);
    cudaFuncSetAttribute(gemm_h<4>, cudaFuncAttributeMaxDynamicSharedMemorySize, GEMMH_SMEM);
    cudaFuncSetAttribute(attn_tc,   cudaFuncAttributeMaxDynamicSharedMemorySize, ATT_SMEM);

    // ---- one-time fp32->fp16 conversions (per launch) ----
    cvt_f32_f16<<<(MM*DD/4 + 255)/256, 256>>>(X,  pXh,  MM*DD);
    cvt_f32_f16<<<(DD*DD/4 + 255)/256, 256>>>(wq, pWqh, DD*DD);
    cvt_f32_f16<<<(DD*DD/4 + 255)/256, 256>>>(wk, pWkh, DD*DD);
    cvt_f32_f16<<<(DD*DD/4 + 255)/256, 256>>>(wv, pWvh, DD*DD);
    cvt_f32_f16<<<(DFF*DD/4 + 255)/256, 256>>>(w1, pW1h, DFF*DD);
    cvt_f32_f16<<<(DD*DFF/4 + 255)/256, 256>>>(w2, pW2h, DD*DFF);

    const dim3 blk(128);
    // Fused QKV projection (blockIdx.z selects weight/output)
    gemm_h<3><<<dim3(DD/128, MM/128, 3), blk, GEMMH_SMEM>>>(
        pXh, pWqh, pWkh, pWvh, pQ, pK, pV, nullptr, nullptr, MM, DD, DD);
    attn_tc<<<dim3(LL/64, BB*HH), 128, ATT_SMEM>>>(pQ, pK, pV, pCtx);
    ln_kernel<<<MM, 256>>>(X, pCtx, nullptr, nullptr, ln1_g, ln1_b, pX1, pX1h);
    // FFN up + SELU -> fp16 Hb
    gemm_h<1><<<dim3(DFF/128, MM/128), blk, GEMMH_SMEM>>>(
        pX1h, pW1h, nullptr, nullptr, nullptr, nullptr, nullptr, pHbh, b1,
        MM, DFF, DD);
    // FFN down, split-K=2 -> fp32 partials
    gemm_h<4><<<dim3(DD/128, MM/128, 2), blk, GEMMH_SMEM>>>(
        pHbh, pW2h, nullptr, nullptr, pY, pY2, nullptr, nullptr, nullptr,
        MM, DD, DFF);
    // LN2( Y + Y2 + X1 + b2 ) -> out
    ln_kernel<<<MM, 256>>>(pY, pY2, pX1, b2, ln2_g, ln2_b, out, nullptr);
}